// round 10
// baseline (speedup 1.0000x reference)
#include <cuda_runtime.h>

// Hausdorff distance, batched N=8, grid 96x96, coords (i/96, j/96).
// haus[s] = max(directed(A\B -> B), directed(B\A -> A)), out = mean over s.
// Single fused pass: warp w owns rows 3w..3w+2, lane owns j = lane,+32,+64.
// Row masks built in-register via ballot; rd2 via clz/ffs; one barrier total;
// early-exit outward column scan (branchless clamped) for the directed max.

#define HD 96
#define WD 96
#define HW (HD * WD)
#define NT 1024

__device__ float        g_dir[64];     // [s*2 + dir]
__device__ unsigned int g_count = 0;   // self-resetting last-block counter

__global__ void __launch_bounds__(NT) hausdorff_kernel(
    const float* __restrict__ pred, const float* __restrict__ targ,
    float* __restrict__ out, int n) {
    __shared__ unsigned short s_rd2[HW];   // squared row distance (sentinel 40000)
    __shared__ int s_red[32];

    const int s    = blockIdx.x;
    const int dir  = blockIdx.y;           // 0: tgt=B, src=A&~B ; 1: tgt=A, src=B&~A
    const int tid  = threadIdx.x;
    const int lane = tid & 31;
    const int wrp  = tid >> 5;             // 0..31 -> rows 3w..3w+2

    const float* __restrict__ P = pred + s * HW;
    const float* __restrict__ T = targ + s * HW;

    // ---- Load this warp's 3 rows (both arrays), 18 coalesced scalar loads.
    float av[9], bv[9];
    #pragma unroll
    for (int rr = 0; rr < 3; rr++) {
        const int base = (wrp * 3 + rr) * WD + lane;
        #pragma unroll
        for (int c = 0; c < 3; c++) {
            av[rr * 3 + c] = P[base + 32 * c];
            bv[rr * 3 + c] = T[base + 32 * c];
        }
    }

    // ---- Build row masks via ballot; compute rd2 straight from registers.
    unsigned srcbits = 0;            // bit rr*3+c: this lane's pixel is a source
    unsigned anyT = 0;
    int rd2own[9];
    #pragma unroll
    for (int rr = 0; rr < 3; rr++) {
        unsigned tm[3];
        #pragma unroll
        for (int c = 0; c < 3; c++) {
            bool a = av[rr * 3 + c] > 0.5f;   // round(x)>0.5 <=> x>0.5 on [0,1)
            bool b = bv[rr * 3 + c] > 0.5f;
            unsigned am = __ballot_sync(0xffffffffu, a);
            unsigned bm = __ballot_sync(0xffffffffu, b);
            tm[c] = dir ? am : bm;
            bool src = dir ? (b && !a) : (a && !b);
            srcbits |= (unsigned)src << (rr * 3 + c);
        }
        anyT |= tm[0] | tm[1] | tm[2];

        const unsigned long long lo = (unsigned long long)tm[0]
                                    | ((unsigned long long)tm[1] << 32);
        const unsigned hi = tm[2];
        int v0, v1, v2;
        {   // j = lane (0..31)
            const int j = lane;
            unsigned long long x = lo & (~0ULL >> (63 - j));
            int dl = x ? (j - (63 - __clzll(x))) : 200;
            unsigned long long y = lo >> j;
            int dr = y ? (__ffsll(y) - 1) : (hi ? (64 - j) + __ffs(hi) - 1 : 200);
            v0 = min(dl, dr);
        }
        {   // j = lane+32 (32..63)
            const int j = lane + 32;
            unsigned long long x = lo & (~0ULL >> (63 - j));
            int dl = x ? (j - (63 - __clzll(x))) : 200;
            unsigned long long y = lo >> j;
            int dr = y ? (__ffsll(y) - 1) : (hi ? (64 - j) + __ffs(hi) - 1 : 200);
            v1 = min(dl, dr);
        }
        {   // j = lane+64 (64..95)
            const int j = lane + 64;
            unsigned x = hi & (~0u >> (31 - lane));
            int dl;
            if (x)       dl = j - (64 + 31 - __clz(x));
            else if (lo) dl = j - (63 - __clzll(lo));
            else         dl = 200;
            unsigned y = hi >> lane;
            int dr = y ? (__ffs(y) - 1) : 200;
            v2 = min(dl, dr);
        }
        const int i = wrp * 3 + rr;
        rd2own[rr * 3 + 0] = v0 * v0;
        rd2own[rr * 3 + 1] = v1 * v1;
        rd2own[rr * 3 + 2] = v2 * v2;
        s_rd2[i * WD + lane]      = (unsigned short)(v0 * v0);
        s_rd2[i * WD + lane + 32] = (unsigned short)(v1 * v1);
        s_rd2[i * WD + lane + 64] = (unsigned short)(v2 * v2);
    }

    // Single barrier: global anyTgt OR + makes s_rd2 visible block-wide.
    const int anyTgt = __syncthreads_or((int)(anyT != 0));

    // ---- Early-exit outward column scan (dense ownership, 9 px/thread).
    // Clamped boundary reads only duplicate candidates already covered => min safe.
    int best = -1;
    #pragma unroll
    for (int rr = 0; rr < 3; rr++) {
        const int i = wrp * 3 + rr;
        #pragma unroll
        for (int c = 0; c < 3; c++) {
            const int j = lane + 32 * c;
            int bst = ((srcbits >> (rr * 3 + c)) & 1u) ? rd2own[rr * 3 + c] : -1;
            int d2 = 1;
            for (int di = 1; d2 < bst; d2 += 2 * di + 1, di++) {
                int u = max(i - di, 0) * WD + j;
                int v = min(i + di, HD - 1) * WD + j;
                bst = min(bst, d2 + (int)s_rd2[u]);
                bst = min(bst, d2 + (int)s_rd2[v]);
            }
            best = max(best, bst);
        }
    }

    // ---- Block max-reduction
    #pragma unroll
    for (int off = 16; off > 0; off >>= 1)
        best = max(best, __shfl_xor_sync(0xffffffffu, best, off));
    if (lane == 0) s_red[wrp] = best;
    __syncthreads();
    if (wrp == 0) {
        int m = s_red[lane];
        #pragma unroll
        for (int off = 16; off > 0; off >>= 1)
            m = max(m, __shfl_xor_sync(0xffffffffu, m, off));
        if (lane == 0) {
            float r;
            if (m < 0)        r = 0.0f;                  // empty source set
            else if (!anyTgt) r = 1e9f;                  // src nonempty, tgt empty
            else              r = sqrtf((float)m) * (1.0f / 96.0f);
            g_dir[s * 2 + dir] = r;
            __threadfence();
            unsigned int t = atomicAdd(&g_count, 1);
            if (t == (unsigned int)(2 * n - 1)) {        // last block: finish + reset
                __threadfence();
                volatile float* gd = g_dir;
                float acc = 0.0f;
                for (int i = 0; i < n; i++)
                    acc += fmaxf(gd[2 * i], gd[2 * i + 1]);
                out[0] = acc / (float)n;
                g_count = 0;                             // self-reset for next replay
            }
        }
    }
}

extern "C" void kernel_launch(void* const* d_in, const int* in_sizes, int n_in,
                              void* d_out, int out_size) {
    const float* pred = (const float*)d_in[0];
    const float* targ = (const float*)d_in[1];
    float* out = (float*)d_out;
    int n = in_sizes[0] / HW;   // batch size (8)

    dim3 grid(n, 2);
    hausdorff_kernel<<<grid, NT>>>(pred, targ, out, n);
}

// round 11
// speedup vs baseline: 1.0819x; 1.0819x over previous
#include <cuda_runtime.h>

// Hausdorff distance, batched N=8, grid 96x96, coords (i/96, j/96).
// haus[s] = max(directed(A\B -> B), directed(B\A -> A)), out = mean over s.
// Single fused pass: warp w owns rows 3w..3w+2, lane owns j = lane,+32,+64.
// Row masks in-register via ballot; rd2 via clz/ffs; one main barrier;
// column scan: branchless unrolled di=1..3 probes + rare divergent tail.

#define HD 96
#define WD 96
#define HW (HD * WD)
#define NT 1024

__device__ float        g_dir[64];     // [s*2 + dir]
__device__ unsigned int g_count = 0;   // self-resetting last-block counter

__global__ void __launch_bounds__(NT) hausdorff_kernel(
    const float* __restrict__ pred, const float* __restrict__ targ,
    float* __restrict__ out, int n) {
    __shared__ unsigned short s_rd2[HW];   // squared row distance (sentinel 40000)
    __shared__ int s_red[32];

    const int s    = blockIdx.x;
    const int dir  = blockIdx.y;           // 0: tgt=B, src=A&~B ; 1: tgt=A, src=B&~A
    const int tid  = threadIdx.x;
    const int lane = tid & 31;
    const int wrp  = tid >> 5;             // 0..31 -> rows 3w..3w+2

    const float* __restrict__ P = pred + s * HW;
    const float* __restrict__ T = targ + s * HW;

    // ---- Load this warp's 3 rows (both arrays), 18 coalesced scalar loads.
    float av[9], bv[9];
    #pragma unroll
    for (int rr = 0; rr < 3; rr++) {
        const int base = (wrp * 3 + rr) * WD + lane;
        #pragma unroll
        for (int c = 0; c < 3; c++) {
            av[rr * 3 + c] = P[base + 32 * c];
            bv[rr * 3 + c] = T[base + 32 * c];
        }
    }

    // ---- Build row masks via ballot; compute rd2 straight from registers.
    unsigned srcbits = 0;            // bit rr*3+c: this lane's pixel is a source
    unsigned anyT = 0;
    int rd2own[9];
    #pragma unroll
    for (int rr = 0; rr < 3; rr++) {
        unsigned tm[3];
        #pragma unroll
        for (int c = 0; c < 3; c++) {
            bool a = av[rr * 3 + c] > 0.5f;   // round(x)>0.5 <=> x>0.5 on [0,1)
            bool b = bv[rr * 3 + c] > 0.5f;
            unsigned am = __ballot_sync(0xffffffffu, a);
            unsigned bm = __ballot_sync(0xffffffffu, b);
            tm[c] = dir ? am : bm;
            bool src = dir ? (b && !a) : (a && !b);
            srcbits |= (unsigned)src << (rr * 3 + c);
        }
        anyT |= tm[0] | tm[1] | tm[2];

        const unsigned long long lo = (unsigned long long)tm[0]
                                    | ((unsigned long long)tm[1] << 32);
        const unsigned hi = tm[2];
        int v0, v1, v2;
        {   // j = lane (0..31)
            const int j = lane;
            unsigned long long x = lo & (~0ULL >> (63 - j));
            int dl = x ? (j - (63 - __clzll(x))) : 200;
            unsigned long long y = lo >> j;
            int dr = y ? (__ffsll(y) - 1) : (hi ? (64 - j) + __ffs(hi) - 1 : 200);
            v0 = min(dl, dr);
        }
        {   // j = lane+32 (32..63)
            const int j = lane + 32;
            unsigned long long x = lo & (~0ULL >> (63 - j));
            int dl = x ? (j - (63 - __clzll(x))) : 200;
            unsigned long long y = lo >> j;
            int dr = y ? (__ffsll(y) - 1) : (hi ? (64 - j) + __ffs(hi) - 1 : 200);
            v1 = min(dl, dr);
        }
        {   // j = lane+64 (64..95)
            const int j = lane + 64;
            unsigned x = hi & (~0u >> (31 - lane));
            int dl;
            if (x)       dl = j - (64 + 31 - __clz(x));
            else if (lo) dl = j - (63 - __clzll(lo));
            else         dl = 200;
            unsigned y = hi >> lane;
            int dr = y ? (__ffs(y) - 1) : 200;
            v2 = min(dl, dr);
        }
        const int i = wrp * 3 + rr;
        rd2own[rr * 3 + 0] = v0 * v0;
        rd2own[rr * 3 + 1] = v1 * v1;
        rd2own[rr * 3 + 2] = v2 * v2;
        s_rd2[i * WD + lane]      = (unsigned short)(v0 * v0);
        s_rd2[i * WD + lane + 32] = (unsigned short)(v1 * v1);
        s_rd2[i * WD + lane + 64] = (unsigned short)(v2 * v2);
    }

    // Single barrier: global anyTgt OR + makes s_rd2 visible block-wide.
    const int anyTgt = __syncthreads_or((int)(anyT != 0));

    // ---- Column scan: branchless unrolled di=1..3 + rare tail from di=4.
    // Clamped boundary probes only duplicate candidates already covered exactly
    // at smaller di (or duplicate row-0/95 with larger d2) => min unchanged.
    int best = -1;
    #pragma unroll
    for (int rr = 0; rr < 3; rr++) {
        const int i = wrp * 3 + rr;
        #pragma unroll
        for (int c = 0; c < 3; c++) {
            const int j = lane + 32 * c;
            int bst = ((srcbits >> (rr * 3 + c)) & 1u) ? rd2own[rr * 3 + c] : -1;
            int au = i * WD + j;
            int avd = au;
            const int loA = j;                 // row 0 clamp
            const int hiA = 95 * WD + j;       // row 95 clamp
            #pragma unroll
            for (int di = 1; di <= 3; di++) {
                au  = max(au - WD, loA);
                avd = min(avd + WD, hiA);
                bst = min(bst, di * di + (int)s_rd2[au]);
                bst = min(bst, di * di + (int)s_rd2[avd]);
            }
            int di = 4, d2 = 16;
            while (d2 < bst) {                 // rare: only when local rd2 is large
                au  = max(au - WD, loA);
                avd = min(avd + WD, hiA);
                bst = min(bst, d2 + (int)s_rd2[au]);
                bst = min(bst, d2 + (int)s_rd2[avd]);
                di++;
                d2 = di * di;
            }
            best = max(best, bst);
        }
    }

    // ---- Block max-reduction
    #pragma unroll
    for (int off = 16; off > 0; off >>= 1)
        best = max(best, __shfl_xor_sync(0xffffffffu, best, off));
    if (lane == 0) s_red[wrp] = best;
    __syncthreads();
    if (wrp == 0) {
        int m = s_red[lane];
        #pragma unroll
        for (int off = 16; off > 0; off >>= 1)
            m = max(m, __shfl_xor_sync(0xffffffffu, m, off));
        if (lane == 0) {
            float r;
            if (m < 0)        r = 0.0f;                  // empty source set
            else if (!anyTgt) r = 1e9f;                  // src nonempty, tgt empty
            else              r = sqrtf((float)m) * (1.0f / 96.0f);
            g_dir[s * 2 + dir] = r;
            __threadfence();
            unsigned int t = atomicAdd(&g_count, 1);
            if (t == (unsigned int)(2 * n - 1)) {        // last block: finish + reset
                __threadfence();
                volatile float* gd = g_dir;
                float acc = 0.0f;
                for (int i = 0; i < n; i++)
                    acc += fmaxf(gd[2 * i], gd[2 * i + 1]);
                out[0] = acc / (float)n;
                g_count = 0;                             // self-reset for next replay
            }
        }
    }
}

extern "C" void kernel_launch(void* const* d_in, const int* in_sizes, int n_in,
                              void* d_out, int out_size) {
    const float* pred = (const float*)d_in[0];
    const float* targ = (const float*)d_in[1];
    float* out = (float*)d_out;
    int n = in_sizes[0] / HW;   // batch size (8)

    dim3 grid(n, 2);
    hausdorff_kernel<<<grid, NT>>>(pred, targ, out, n);
}